// round 3
// baseline (speedup 1.0000x reference)
#include <cuda_runtime.h>

#define N_NODES 100000
#define N_EDGES 1600000
#define IN_CH 64
#define HID 128
#define OUT_CH 2

// Scratch (static device globals; allocation-free per harness rules)
__device__ float g_cnt[N_NODES];
__device__ float g_agg0[(size_t)N_NODES * IN_CH];
__device__ float g_h1[(size_t)N_NODES * HID];
__device__ float g_agg1[(size_t)N_NODES * HID];

// ---------------------------------------------------------------------------
// Zero scratch (memset nodes on __device__ symbols are not graph-supported)
// ---------------------------------------------------------------------------
__global__ void zero_scratch_kernel() {
    size_t tid = (size_t)blockIdx.x * blockDim.x + threadIdx.x;
    size_t stride = (size_t)gridDim.x * blockDim.x;
    const size_t n0 = (size_t)N_NODES * IN_CH / 4;
    const size_t n1 = (size_t)N_NODES * HID / 4;
    float4 z = make_float4(0.f, 0.f, 0.f, 0.f);
    float4* a0 = (float4*)g_agg0;
    float4* a1 = (float4*)g_agg1;
    for (size_t i = tid; i < n0; i += stride) a0[i] = z;
    for (size_t i = tid; i < n1; i += stride) a1[i] = z;
    for (size_t i = tid; i < N_NODES; i += stride) g_cnt[i] = 0.f;
}

// ---------------------------------------------------------------------------
// Scatter layer 0: agg0[dst] += x[src] (64 ch), plus degree count.
// 16 threads per edge, float4 gather + 4 scalar atomics.
// edge_index is int32 (JAX x64 disabled => int64 request silently int32).
// ---------------------------------------------------------------------------
__global__ void scatter0_kernel(const float* __restrict__ x,
                                const int* __restrict__ ei) {
    int tid = blockIdx.x * blockDim.x + threadIdx.x;   // e*16 + c4
    if (tid >= N_EDGES * 16) return;
    int e  = tid >> 4;
    int c  = (tid & 15) * 4;
    int src = __ldg(&ei[e]);
    int dst = __ldg(&ei[e + N_EDGES]);
    float4 v = *(const float4*)(x + (size_t)src * IN_CH + c);
    float* a = g_agg0 + (size_t)dst * IN_CH + c;
    atomicAdd(a + 0, v.x);
    atomicAdd(a + 1, v.y);
    atomicAdd(a + 2, v.z);
    atomicAdd(a + 3, v.w);
    if ((tid & 15) == 0) atomicAdd(&g_cnt[dst], 1.0f);
}

// ---------------------------------------------------------------------------
// Scatter layer 1: agg1[dst] += h1[src] (128 ch). 32 threads per edge.
// ---------------------------------------------------------------------------
__global__ void scatter1_kernel(const int* __restrict__ ei) {
    int tid = blockIdx.x * blockDim.x + threadIdx.x;   // e*32 + c4
    if (tid >= N_EDGES * 32) return;
    int e  = tid >> 5;
    int c  = (tid & 31) * 4;
    int src = __ldg(&ei[e]);
    int dst = __ldg(&ei[e + N_EDGES]);
    float4 v = *(const float4*)(g_h1 + (size_t)src * HID + c);
    float* a = g_agg1 + (size_t)dst * HID + c;
    atomicAdd(a + 0, v.x);
    atomicAdd(a + 1, v.y);
    atomicAdd(a + 2, v.z);
    atomicAdd(a + 3, v.w);
}

// ---------------------------------------------------------------------------
// Layer 0 GEMM: h1 = relu(mean0 @ Wn0 + x @ Ws0 + b0)
// 256 threads, 2 groups of 128; each group handles 8 nodes, thread = channel.
// Weights (Wn,Ws) interleaved as float2 in SMEM; node rows staged in SMEM.
// ---------------------------------------------------------------------------
__global__ void layer0_kernel(const float* __restrict__ x,
                              const float* __restrict__ Wn,
                              const float* __restrict__ Ws,
                              const float* __restrict__ b) {
    extern __shared__ float sh[];
    float2* sW = (float2*)sh;                 // 64*128 float2 = 64KB
    float*  sM = sh + 2 * IN_CH * HID;        // 16*64 floats
    float*  sX = sM + 16 * IN_CH;             // 16*64 floats

    int t = threadIdx.x;
    for (int i = t; i < IN_CH * HID; i += 256)
        sW[i] = make_float2(__ldg(&Wn[i]), __ldg(&Ws[i]));

    int grp = t >> 7;         // 0/1
    int lt  = t & 127;        // output channel
    int nodeBase = blockIdx.x * 16 + grp * 8;

    float* pM = sM + grp * 8 * IN_CH;
    float* pX = sX + grp * 8 * IN_CH;
    for (int i = lt; i < 8 * IN_CH; i += 128) {
        int ni = i >> 6, k = i & 63;
        int node = nodeBase + ni;
        float xv = 0.f, mv = 0.f;
        if (node < N_NODES) {
            xv = x[(size_t)node * IN_CH + k];
            float c = g_cnt[node];
            mv = g_agg0[(size_t)node * IN_CH + k] / fmaxf(c, 1.0f);
        }
        pX[i] = xv;
        pM[i] = mv;
    }
    __syncthreads();

    float acc[8];
    float bias = __ldg(&b[lt]);
#pragma unroll
    for (int i = 0; i < 8; i++) acc[i] = bias;

    for (int k = 0; k < IN_CH; k += 4) {
        float4 m4[8], x4[8];
#pragma unroll
        for (int i = 0; i < 8; i++) {
            m4[i] = *(const float4*)(pM + i * IN_CH + k);
            x4[i] = *(const float4*)(pX + i * IN_CH + k);
        }
#pragma unroll
        for (int kk = 0; kk < 4; kk++) {
            float2 w = sW[(k + kk) * HID + lt];
#pragma unroll
            for (int i = 0; i < 8; i++) {
                float mvv = (&m4[i].x)[kk];
                float xvv = (&x4[i].x)[kk];
                acc[i] += mvv * w.x + xvv * w.y;
            }
        }
    }

#pragma unroll
    for (int i = 0; i < 8; i++) {
        int node = nodeBase + i;
        if (node < N_NODES)
            g_h1[(size_t)node * HID + lt] = fmaxf(acc[i], 0.0f);
    }
}

// ---------------------------------------------------------------------------
// Layer 1 GEMM + fused FC:
// h2 = relu(mean1 @ Wn1 + h1 @ Ws1 + b1);  out = h2 @ fc_w + fc_b
// ---------------------------------------------------------------------------
__global__ void layer1_kernel(const float* __restrict__ Wn,
                              const float* __restrict__ Ws,
                              const float* __restrict__ b,
                              const float* __restrict__ fcw,
                              const float* __restrict__ fcb,
                              float* __restrict__ out) {
    extern __shared__ float sh[];
    float2* sW = (float2*)sh;                 // 128*128 float2 = 128KB
    float*  sM = sh + 2 * HID * HID;          // 16*128 floats (8KB)
    float*  sX = sM + 16 * HID;               // 16*128 floats (8KB)

    int t = threadIdx.x;
    for (int i = t; i < HID * HID; i += 256)
        sW[i] = make_float2(__ldg(&Wn[i]), __ldg(&Ws[i]));

    int grp = t >> 7;
    int lt  = t & 127;
    int nodeBase = blockIdx.x * 16 + grp * 8;

    float* pM = sM + grp * 8 * HID;
    float* pX = sX + grp * 8 * HID;
    for (int i = lt; i < 8 * HID; i += 128) {
        int ni = i >> 7, k = i & 127;
        int node = nodeBase + ni;
        float hv = 0.f, mv = 0.f;
        if (node < N_NODES) {
            hv = g_h1[(size_t)node * HID + k];
            float c = g_cnt[node];
            mv = g_agg1[(size_t)node * HID + k] / fmaxf(c, 1.0f);
        }
        pX[i] = hv;
        pM[i] = mv;
    }
    __syncthreads();

    float acc[8];
    float bias = __ldg(&b[lt]);
#pragma unroll
    for (int i = 0; i < 8; i++) acc[i] = bias;

    for (int k = 0; k < HID; k += 4) {
        float4 m4[8], x4[8];
#pragma unroll
        for (int i = 0; i < 8; i++) {
            m4[i] = *(const float4*)(pM + i * HID + k);
            x4[i] = *(const float4*)(pX + i * HID + k);
        }
#pragma unroll
        for (int kk = 0; kk < 4; kk++) {
            float2 w = sW[(k + kk) * HID + lt];
#pragma unroll
            for (int i = 0; i < 8; i++) {
                float mvv = (&m4[i].x)[kk];
                float xvv = (&x4[i].x)[kk];
                acc[i] += mvv * w.x + xvv * w.y;
            }
        }
    }
    __syncthreads();   // done reading sM/sX — reuse sM as h2 staging

    // stage relu(h2) rows: sM[ni*128 + lt], ni = local node 0..15
#pragma unroll
    for (int i = 0; i < 8; i++) {
        int ni = grp * 8 + i;
        sM[ni * HID + lt] = fmaxf(acc[i], 0.0f);
    }
    __syncthreads();

    // fused FC: each warp handles 2 nodes
    int w = t >> 5, lane = t & 31;
    float fb0 = __ldg(&fcb[0]), fb1 = __ldg(&fcb[1]);
#pragma unroll
    for (int rep = 0; rep < 2; rep++) {
        int ni = w * 2 + rep;
        int node = blockIdx.x * 16 + ni;
        const float* h2 = sM + ni * HID;
        float p0 = 0.f, p1 = 0.f;
#pragma unroll
        for (int j = lane; j < HID; j += 32) {
            float v = h2[j];
            p0 += v * __ldg(&fcw[j * 2 + 0]);
            p1 += v * __ldg(&fcw[j * 2 + 1]);
        }
#pragma unroll
        for (int off = 16; off > 0; off >>= 1) {
            p0 += __shfl_xor_sync(0xFFFFFFFF, p0, off);
            p1 += __shfl_xor_sync(0xFFFFFFFF, p1, off);
        }
        if (lane == 0 && node < N_NODES) {
            out[(size_t)node * 2 + 0] = p0 + fb0;
            out[(size_t)node * 2 + 1] = p1 + fb1;
        }
    }
}

// ---------------------------------------------------------------------------
extern "C" void kernel_launch(void* const* d_in, const int* in_sizes, int n_in,
                              void* d_out, int out_size) {
    const float* x    = (const float*)d_in[0];
    const int*   ei   = (const int*)d_in[1];     // int32! (JAX x64 disabled)
    const float* Wn0  = (const float*)d_in[2];
    const float* Ws0  = (const float*)d_in[3];
    const float* b0   = (const float*)d_in[4];
    const float* Wn1  = (const float*)d_in[5];
    const float* Ws1  = (const float*)d_in[6];
    const float* b1   = (const float*)d_in[7];
    const float* fcw  = (const float*)d_in[8];
    const float* fcb  = (const float*)d_in[9];
    float* out = (float*)d_out;

    // Zero scratch via kernel (graph-capturable, unlike memset on symbols)
    zero_scratch_kernel<<<1184, 256>>>();

    // Scatter layer 0 (+ degree)
    {
        int threads = 256;
        int blocks = (N_EDGES * 16 + threads - 1) / threads;
        scatter0_kernel<<<blocks, threads>>>(x, ei);
    }

    // Layer 0 GEMM
    {
        int smem0 = (2 * IN_CH * HID + 2 * 16 * IN_CH) * (int)sizeof(float); // 72KB
        cudaFuncSetAttribute(layer0_kernel,
                             cudaFuncAttributeMaxDynamicSharedMemorySize, smem0);
        int blocks = (N_NODES + 15) / 16;
        layer0_kernel<<<blocks, 256, smem0>>>(x, Wn0, Ws0, b0);
    }

    // Scatter layer 1
    {
        int threads = 256;
        int blocks = (N_EDGES * 32 + threads - 1) / threads;
        scatter1_kernel<<<blocks, threads>>>(ei);
    }

    // Layer 1 GEMM + fused FC
    {
        int smem1 = (2 * HID * HID + 2 * 16 * HID) * (int)sizeof(float);     // 144KB
        cudaFuncSetAttribute(layer1_kernel,
                             cudaFuncAttributeMaxDynamicSharedMemorySize, smem1);
        int blocks = (N_NODES + 15) / 16;
        layer1_kernel<<<blocks, 256, smem1>>>(Wn1, Ws1, b1, fcw, fcb, out);
    }
}

// round 4
// speedup vs baseline: 1.3633x; 1.3633x over previous
#include <cuda_runtime.h>

#define N_NODES 100000
#define N_EDGES 1600000
#define IN_CH 64
#define HID 128
#define OUT_CH 2

// Scratch (static device globals; allocation-free per harness rules)
__device__ int   g_deg[N_NODES];
__device__ int   g_cursor[N_NODES];
__device__ int   g_row_ptr[N_NODES + 1];
__device__ int   g_srcs[N_EDGES];
__device__ float g_mean0[(size_t)N_NODES * IN_CH];
__device__ float g_h1[(size_t)N_NODES * HID];
__device__ float g_mean1[(size_t)N_NODES * HID];

// ---------------------------------------------------------------------------
// CSR build step 1: zero degree array
// ---------------------------------------------------------------------------
__global__ void zero_deg_kernel() {
    int i = blockIdx.x * blockDim.x + threadIdx.x;
    if (i < N_NODES) g_deg[i] = 0;
}

// CSR build step 2: degree histogram over dst
__global__ void hist_kernel(const int* __restrict__ ei) {
    int e = blockIdx.x * blockDim.x + threadIdx.x;
    if (e >= N_EDGES) return;
    atomicAdd(&g_deg[__ldg(&ei[e + N_EDGES])], 1);
}

// CSR build step 3: exclusive scan (single block, 1024 threads)
__global__ void scan_kernel() {
    __shared__ int sm[1024];
    const int CH = (N_NODES + 1023) / 1024;   // 98
    int t = threadIdx.x;
    int beg = t * CH;
    int end = beg + CH; if (end > N_NODES) end = N_NODES;
    int s = 0;
    for (int i = beg; i < end; i++) s += g_deg[i];
    sm[t] = s;
    __syncthreads();
    // Hillis-Steele inclusive scan
    for (int off = 1; off < 1024; off <<= 1) {
        int v = (t >= off) ? sm[t - off] : 0;
        __syncthreads();
        sm[t] += v;
        __syncthreads();
    }
    int prefix = (t == 0) ? 0 : sm[t - 1];
    for (int i = beg; i < end; i++) {
        g_row_ptr[i] = prefix;
        g_cursor[i]  = prefix;
        prefix += g_deg[i];
    }
    if (t == 1023) g_row_ptr[N_NODES] = sm[1023];
}

// CSR build step 4: fill src lists (order within a dst is arbitrary — fp sum OK)
__global__ void fill_kernel(const int* __restrict__ ei) {
    int e = blockIdx.x * blockDim.x + threadIdx.x;
    if (e >= N_EDGES) return;
    int src = __ldg(&ei[e]);
    int dst = __ldg(&ei[e + N_EDGES]);
    int pos = atomicAdd(&g_cursor[dst], 1);
    g_srcs[pos] = src;
}

// ---------------------------------------------------------------------------
// Gather layer 0: mean0[n] = mean over edges of x[src] (64 ch).
// Warp per node; lane holds float2 (64 ch / 32 lanes).
// ---------------------------------------------------------------------------
__global__ void gather0_kernel(const float* __restrict__ x) {
    int node = blockIdx.x * 8 + (threadIdx.x >> 5);
    if (node >= N_NODES) return;
    int lane = threadIdx.x & 31;
    int beg = g_row_ptr[node], end = g_row_ptr[node + 1];
    float2 acc = make_float2(0.f, 0.f);
    int e = beg;
#pragma unroll 4
    for (; e < end; e++) {
        int s = __ldg(&g_srcs[e]);
        float2 v = *(const float2*)(x + (size_t)s * IN_CH + lane * 2);
        acc.x += v.x; acc.y += v.y;
    }
    float inv = 1.0f / fmaxf((float)(end - beg), 1.0f);
    acc.x *= inv; acc.y *= inv;
    *(float2*)(g_mean0 + (size_t)node * IN_CH + lane * 2) = acc;
}

// ---------------------------------------------------------------------------
// Gather layer 1: mean1[n] = mean over edges of h1[src] (128 ch).
// Warp per node; lane holds float4 (128 ch / 32 lanes).
// ---------------------------------------------------------------------------
__global__ void gather1_kernel() {
    int node = blockIdx.x * 8 + (threadIdx.x >> 5);
    if (node >= N_NODES) return;
    int lane = threadIdx.x & 31;
    int beg = g_row_ptr[node], end = g_row_ptr[node + 1];
    float4 acc = make_float4(0.f, 0.f, 0.f, 0.f);
    int e = beg;
#pragma unroll 4
    for (; e < end; e++) {
        int s = __ldg(&g_srcs[e]);
        float4 v = *(const float4*)(g_h1 + (size_t)s * HID + lane * 4);
        acc.x += v.x; acc.y += v.y; acc.z += v.z; acc.w += v.w;
    }
    float inv = 1.0f / fmaxf((float)(end - beg), 1.0f);
    acc.x *= inv; acc.y *= inv; acc.z *= inv; acc.w *= inv;
    *(float4*)(g_mean1 + (size_t)node * HID + lane * 4) = acc;
}

// ---------------------------------------------------------------------------
// Layer 0 GEMM: h1 = relu(mean0 @ Wn0 + x @ Ws0 + b0)
// 256 threads, 2 groups of 128; each group handles 8 nodes, thread = channel.
// ---------------------------------------------------------------------------
__global__ void layer0_kernel(const float* __restrict__ x,
                              const float* __restrict__ Wn,
                              const float* __restrict__ Ws,
                              const float* __restrict__ b) {
    extern __shared__ float sh[];
    float2* sW = (float2*)sh;                 // 64*128 float2 = 64KB
    float*  sM = sh + 2 * IN_CH * HID;        // 16*64 floats
    float*  sX = sM + 16 * IN_CH;             // 16*64 floats

    int t = threadIdx.x;
    for (int i = t; i < IN_CH * HID; i += 256)
        sW[i] = make_float2(__ldg(&Wn[i]), __ldg(&Ws[i]));

    int grp = t >> 7;         // 0/1
    int lt  = t & 127;        // output channel
    int nodeBase = blockIdx.x * 16 + grp * 8;

    float* pM = sM + grp * 8 * IN_CH;
    float* pX = sX + grp * 8 * IN_CH;
    for (int i = lt; i < 8 * IN_CH; i += 128) {
        int ni = i >> 6, k = i & 63;
        int node = nodeBase + ni;
        float xv = 0.f, mv = 0.f;
        if (node < N_NODES) {
            xv = x[(size_t)node * IN_CH + k];
            mv = g_mean0[(size_t)node * IN_CH + k];
        }
        pX[i] = xv;
        pM[i] = mv;
    }
    __syncthreads();

    float acc[8];
    float bias = __ldg(&b[lt]);
#pragma unroll
    for (int i = 0; i < 8; i++) acc[i] = bias;

    for (int k = 0; k < IN_CH; k += 4) {
        float4 m4[8], x4[8];
#pragma unroll
        for (int i = 0; i < 8; i++) {
            m4[i] = *(const float4*)(pM + i * IN_CH + k);
            x4[i] = *(const float4*)(pX + i * IN_CH + k);
        }
#pragma unroll
        for (int kk = 0; kk < 4; kk++) {
            float2 w = sW[(k + kk) * HID + lt];
#pragma unroll
            for (int i = 0; i < 8; i++) {
                float mvv = (&m4[i].x)[kk];
                float xvv = (&x4[i].x)[kk];
                acc[i] += mvv * w.x + xvv * w.y;
            }
        }
    }

#pragma unroll
    for (int i = 0; i < 8; i++) {
        int node = nodeBase + i;
        if (node < N_NODES)
            g_h1[(size_t)node * HID + lt] = fmaxf(acc[i], 0.0f);
    }
}

// ---------------------------------------------------------------------------
// Layer 1 GEMM + fused FC:
// h2 = relu(mean1 @ Wn1 + h1 @ Ws1 + b1);  out = h2 @ fc_w + fc_b
// ---------------------------------------------------------------------------
__global__ void layer1_kernel(const float* __restrict__ Wn,
                              const float* __restrict__ Ws,
                              const float* __restrict__ b,
                              const float* __restrict__ fcw,
                              const float* __restrict__ fcb,
                              float* __restrict__ out) {
    extern __shared__ float sh[];
    float2* sW = (float2*)sh;                 // 128*128 float2 = 128KB
    float*  sM = sh + 2 * HID * HID;          // 16*128 floats (8KB)
    float*  sX = sM + 16 * HID;               // 16*128 floats (8KB)

    int t = threadIdx.x;
    for (int i = t; i < HID * HID; i += 256)
        sW[i] = make_float2(__ldg(&Wn[i]), __ldg(&Ws[i]));

    int grp = t >> 7;
    int lt  = t & 127;
    int nodeBase = blockIdx.x * 16 + grp * 8;

    float* pM = sM + grp * 8 * HID;
    float* pX = sX + grp * 8 * HID;
    for (int i = lt; i < 8 * HID; i += 128) {
        int ni = i >> 7, k = i & 127;
        int node = nodeBase + ni;
        float hv = 0.f, mv = 0.f;
        if (node < N_NODES) {
            hv = g_h1[(size_t)node * HID + k];
            mv = g_mean1[(size_t)node * HID + k];
        }
        pX[i] = hv;
        pM[i] = mv;
    }
    __syncthreads();

    float acc[8];
    float bias = __ldg(&b[lt]);
#pragma unroll
    for (int i = 0; i < 8; i++) acc[i] = bias;

    for (int k = 0; k < HID; k += 4) {
        float4 m4[8], x4[8];
#pragma unroll
        for (int i = 0; i < 8; i++) {
            m4[i] = *(const float4*)(pM + i * HID + k);
            x4[i] = *(const float4*)(pX + i * HID + k);
        }
#pragma unroll
        for (int kk = 0; kk < 4; kk++) {
            float2 w = sW[(k + kk) * HID + lt];
#pragma unroll
            for (int i = 0; i < 8; i++) {
                float mvv = (&m4[i].x)[kk];
                float xvv = (&x4[i].x)[kk];
                acc[i] += mvv * w.x + xvv * w.y;
            }
        }
    }
    __syncthreads();   // done reading sM/sX — reuse sM as h2 staging

    // stage relu(h2) rows: sM[ni*128 + lt], ni = local node 0..15
#pragma unroll
    for (int i = 0; i < 8; i++) {
        int ni = grp * 8 + i;
        sM[ni * HID + lt] = fmaxf(acc[i], 0.0f);
    }
    __syncthreads();

    // fused FC: each warp handles 2 nodes
    int w = t >> 5, lane = t & 31;
    float fb0 = __ldg(&fcb[0]), fb1 = __ldg(&fcb[1]);
#pragma unroll
    for (int rep = 0; rep < 2; rep++) {
        int ni = w * 2 + rep;
        int node = blockIdx.x * 16 + ni;
        const float* h2 = sM + ni * HID;
        float p0 = 0.f, p1 = 0.f;
#pragma unroll
        for (int j = lane; j < HID; j += 32) {
            float v = h2[j];
            p0 += v * __ldg(&fcw[j * 2 + 0]);
            p1 += v * __ldg(&fcw[j * 2 + 1]);
        }
#pragma unroll
        for (int off = 16; off > 0; off >>= 1) {
            p0 += __shfl_xor_sync(0xFFFFFFFF, p0, off);
            p1 += __shfl_xor_sync(0xFFFFFFFF, p1, off);
        }
        if (lane == 0 && node < N_NODES) {
            out[(size_t)node * 2 + 0] = p0 + fb0;
            out[(size_t)node * 2 + 1] = p1 + fb1;
        }
    }
}

// ---------------------------------------------------------------------------
extern "C" void kernel_launch(void* const* d_in, const int* in_sizes, int n_in,
                              void* d_out, int out_size) {
    const float* x    = (const float*)d_in[0];
    const int*   ei   = (const int*)d_in[1];     // int32 (JAX x64 disabled)
    const float* Wn0  = (const float*)d_in[2];
    const float* Ws0  = (const float*)d_in[3];
    const float* b0   = (const float*)d_in[4];
    const float* Wn1  = (const float*)d_in[5];
    const float* Ws1  = (const float*)d_in[6];
    const float* b1   = (const float*)d_in[7];
    const float* fcw  = (const float*)d_in[8];
    const float* fcb  = (const float*)d_in[9];
    float* out = (float*)d_out;

    // --- CSR build ---
    zero_deg_kernel<<<(N_NODES + 255) / 256, 256>>>();
    hist_kernel<<<(N_EDGES + 255) / 256, 256>>>(ei);
    scan_kernel<<<1, 1024>>>();
    fill_kernel<<<(N_EDGES + 255) / 256, 256>>>(ei);

    // --- Layer 0: gather mean, then GEMM ---
    gather0_kernel<<<(N_NODES + 7) / 8, 256>>>(x);
    {
        int smem0 = (2 * IN_CH * HID + 2 * 16 * IN_CH) * (int)sizeof(float); // 72KB
        cudaFuncSetAttribute(layer0_kernel,
                             cudaFuncAttributeMaxDynamicSharedMemorySize, smem0);
        layer0_kernel<<<(N_NODES + 15) / 16, 256, smem0>>>(x, Wn0, Ws0, b0);
    }

    // --- Layer 1: gather mean, then GEMM + fused FC ---
    gather1_kernel<<<(N_NODES + 7) / 8, 256>>>();
    {
        int smem1 = (2 * HID * HID + 2 * 16 * HID) * (int)sizeof(float);     // 144KB
        cudaFuncSetAttribute(layer1_kernel,
                             cudaFuncAttributeMaxDynamicSharedMemorySize, smem1);
        layer1_kernel<<<(N_NODES + 15) / 16, 256, smem1>>>(Wn1, Ws1, b1, fcw, fcb, out);
    }
}

// round 5
// speedup vs baseline: 2.1968x; 1.6113x over previous
#include <cuda_runtime.h>

#define N_NODES 100000
#define N_EDGES 1600000
#define IN_CH 64
#define HID 128
#define OUT_CH 2

typedef unsigned long long ull;

// Scratch (static device globals; allocation-free per harness rules)
__device__ int   g_deg[N_NODES];
__device__ int   g_cursor[N_NODES];
__device__ int   g_row_ptr[N_NODES + 1];
__device__ int   g_srcs[N_EDGES];
__device__ float g_mean0[(size_t)N_NODES * IN_CH];
__device__ float g_h1[(size_t)N_NODES * HID];
__device__ float g_mean1[(size_t)N_NODES * HID];

// ---------------------------------------------------------------------------
// f32x2 packed-math helpers (Blackwell): 2 fp32 FMAs per issue slot
// ---------------------------------------------------------------------------
__device__ __forceinline__ ull pack2(float v) {
    unsigned u = __float_as_uint(v);
    ull r;
    asm("mov.b64 %0, {%1, %1};" : "=l"(r) : "r"(u));
    return r;
}
__device__ __forceinline__ void fma2(ull& d, ull a, ull b) {
    asm("fma.rn.f32x2 %0, %1, %2, %0;" : "+l"(d) : "l"(a), "l"(b));
}
__device__ __forceinline__ float2 unpack2(ull v) {
    unsigned lo, hi;
    asm("mov.b64 {%0, %1}, %2;" : "=r"(lo), "=r"(hi) : "l"(v));
    return make_float2(__uint_as_float(lo), __uint_as_float(hi));
}

// ---------------------------------------------------------------------------
// CSR build
// ---------------------------------------------------------------------------
__global__ void zero_deg_kernel() {
    int i = blockIdx.x * blockDim.x + threadIdx.x;
    if (i < N_NODES) g_deg[i] = 0;
}

__global__ void hist_kernel(const int* __restrict__ ei) {
    int e = blockIdx.x * blockDim.x + threadIdx.x;
    if (e >= N_EDGES) return;
    atomicAdd(&g_deg[__ldg(&ei[e + N_EDGES])], 1);
}

__global__ void scan_kernel() {
    __shared__ int sm[1024];
    const int CH = (N_NODES + 1023) / 1024;
    int t = threadIdx.x;
    int beg = t * CH;
    int end = beg + CH; if (end > N_NODES) end = N_NODES;
    int s = 0;
    for (int i = beg; i < end; i++) s += g_deg[i];
    sm[t] = s;
    __syncthreads();
    for (int off = 1; off < 1024; off <<= 1) {
        int v = (t >= off) ? sm[t - off] : 0;
        __syncthreads();
        sm[t] += v;
        __syncthreads();
    }
    int prefix = (t == 0) ? 0 : sm[t - 1];
    for (int i = beg; i < end; i++) {
        g_row_ptr[i] = prefix;
        g_cursor[i]  = prefix;
        prefix += g_deg[i];
    }
    if (t == 1023) g_row_ptr[N_NODES] = sm[1023];
}

__global__ void fill_kernel(const int* __restrict__ ei) {
    int e = blockIdx.x * blockDim.x + threadIdx.x;
    if (e >= N_EDGES) return;
    int src = __ldg(&ei[e]);
    int dst = __ldg(&ei[e + N_EDGES]);
    int pos = atomicAdd(&g_cursor[dst], 1);
    g_srcs[pos] = src;
}

// ---------------------------------------------------------------------------
// Gathers: warp per node, CSR edge list (no float atomics)
// ---------------------------------------------------------------------------
__global__ void gather0_kernel(const float* __restrict__ x) {
    int node = blockIdx.x * 8 + (threadIdx.x >> 5);
    if (node >= N_NODES) return;
    int lane = threadIdx.x & 31;
    int beg = g_row_ptr[node], end = g_row_ptr[node + 1];
    float2 acc = make_float2(0.f, 0.f);
#pragma unroll 4
    for (int e = beg; e < end; e++) {
        int s = __ldg(&g_srcs[e]);
        float2 v = *(const float2*)(x + (size_t)s * IN_CH + lane * 2);
        acc.x += v.x; acc.y += v.y;
    }
    float inv = 1.0f / fmaxf((float)(end - beg), 1.0f);
    acc.x *= inv; acc.y *= inv;
    *(float2*)(g_mean0 + (size_t)node * IN_CH + lane * 2) = acc;
}

__global__ void gather1_kernel() {
    int node = blockIdx.x * 8 + (threadIdx.x >> 5);
    if (node >= N_NODES) return;
    int lane = threadIdx.x & 31;
    int beg = g_row_ptr[node], end = g_row_ptr[node + 1];
    float4 acc = make_float4(0.f, 0.f, 0.f, 0.f);
#pragma unroll 4
    for (int e = beg; e < end; e++) {
        int s = __ldg(&g_srcs[e]);
        float4 v = *(const float4*)(g_h1 + (size_t)s * HID + lane * 4);
        acc.x += v.x; acc.y += v.y; acc.z += v.z; acc.w += v.w;
    }
    float inv = 1.0f / fmaxf((float)(end - beg), 1.0f);
    acc.x *= inv; acc.y *= inv; acc.z *= inv; acc.w *= inv;
    *(float4*)(g_mean1 + (size_t)node * HID + lane * 4) = acc;
}

// ---------------------------------------------------------------------------
// Register-blocked f32x2 GEMM, 128 nodes x 128 out per block.
// Thread tile: 8 nodes (4 f32x2 pairs) x 8 out channels.
// K staged in transposed 32-k slices: s[k][node], row padded to 132 floats.
// ---------------------------------------------------------------------------
#define ROWP 132   // padded row (128 nodes + 4)

// Layer 0: h1 = relu(mean0 @ Wn0 + x @ Ws0 + b0), K = 64
__global__ __launch_bounds__(256, 1)
void layer0_kernel(const float* __restrict__ x,
                   const float* __restrict__ Wn,
                   const float* __restrict__ Ws,
                   const float* __restrict__ b) {
    extern __shared__ float sh[];
    float* sWn = sh;                       // 64*128 = 8192
    float* sWs = sWn + IN_CH * HID;        // 8192
    float* sM  = sWs + IN_CH * HID;        // 32*132 = 4224
    float* sX  = sM + 32 * ROWP;           // 4224

    int t = threadIdx.x;
    for (int i = t; i < IN_CH * HID; i += 256) { sWn[i] = Wn[i]; sWs[i] = Ws[i]; }

    int nodeBase = blockIdx.x * 128;
    int jn0 = (t >> 4) * 8;        // out-channel block
    int in0 = (t & 15) * 8;        // local node block

    ull acc[4][8];
#pragma unroll
    for (int jj = 0; jj < 8; jj++) {
        ull bb = pack2(__ldg(&b[jn0 + jj]));
#pragma unroll
        for (int p = 0; p < 4; p++) acc[p][jj] = bb;
    }

    for (int s = 0; s < IN_CH / 32; s++) {
        __syncthreads();
        for (int r = t; r < 128 * 8; r += 256) {
            int node = r >> 3;
            int kq = (r & 7) * 4;
            int gn = nodeBase + node;
            float4 vm = make_float4(0.f, 0.f, 0.f, 0.f), vx = vm;
            if (gn < N_NODES) {
                vm = *(const float4*)(g_mean0 + (size_t)gn * IN_CH + s * 32 + kq);
                vx = *(const float4*)(x       + (size_t)gn * IN_CH + s * 32 + kq);
            }
            sM[(kq + 0) * ROWP + node] = vm.x; sM[(kq + 1) * ROWP + node] = vm.y;
            sM[(kq + 2) * ROWP + node] = vm.z; sM[(kq + 3) * ROWP + node] = vm.w;
            sX[(kq + 0) * ROWP + node] = vx.x; sX[(kq + 1) * ROWP + node] = vx.y;
            sX[(kq + 2) * ROWP + node] = vx.z; sX[(kq + 3) * ROWP + node] = vx.w;
        }
        __syncthreads();
#pragma unroll 2
        for (int k = 0; k < 32; k++) {
            const ull* rowM = (const ull*)(sM + k * ROWP) + (in0 >> 1);
            const ull* rowX = (const ull*)(sX + k * ROWP) + (in0 >> 1);
            ull m[4], xv[4];
#pragma unroll
            for (int p = 0; p < 4; p++) { m[p] = rowM[p]; xv[p] = rowX[p]; }
            const float* wnr = sWn + (s * 32 + k) * HID + jn0;
            const float* wsr = sWs + (s * 32 + k) * HID + jn0;
            float4 wna = *(const float4*)wnr, wnb = *(const float4*)(wnr + 4);
            float4 wsa = *(const float4*)wsr, wsb = *(const float4*)(wsr + 4);
            float wn[8] = {wna.x, wna.y, wna.z, wna.w, wnb.x, wnb.y, wnb.z, wnb.w};
            float ws[8] = {wsa.x, wsa.y, wsa.z, wsa.w, wsb.x, wsb.y, wsb.z, wsb.w};
#pragma unroll
            for (int jj = 0; jj < 8; jj++) {
                ull wn2 = pack2(wn[jj]);
#pragma unroll
                for (int p = 0; p < 4; p++) fma2(acc[p][jj], m[p], wn2);
                ull ws2 = pack2(ws[jj]);
#pragma unroll
                for (int p = 0; p < 4; p++) fma2(acc[p][jj], xv[p], ws2);
            }
        }
    }

    // epilogue: relu -> g_h1
#pragma unroll
    for (int p = 0; p < 4; p++) {
        float2 v[8];
#pragma unroll
        for (int jj = 0; jj < 8; jj++) v[jj] = unpack2(acc[p][jj]);
        int n0 = nodeBase + in0 + 2 * p;
        if (n0 < N_NODES) {
            float4 a = make_float4(fmaxf(v[0].x, 0.f), fmaxf(v[1].x, 0.f),
                                   fmaxf(v[2].x, 0.f), fmaxf(v[3].x, 0.f));
            float4 c = make_float4(fmaxf(v[4].x, 0.f), fmaxf(v[5].x, 0.f),
                                   fmaxf(v[6].x, 0.f), fmaxf(v[7].x, 0.f));
            *(float4*)(g_h1 + (size_t)n0 * HID + jn0) = a;
            *(float4*)(g_h1 + (size_t)n0 * HID + jn0 + 4) = c;
        }
        if (n0 + 1 < N_NODES) {
            float4 a = make_float4(fmaxf(v[0].y, 0.f), fmaxf(v[1].y, 0.f),
                                   fmaxf(v[2].y, 0.f), fmaxf(v[3].y, 0.f));
            float4 c = make_float4(fmaxf(v[4].y, 0.f), fmaxf(v[5].y, 0.f),
                                   fmaxf(v[6].y, 0.f), fmaxf(v[7].y, 0.f));
            *(float4*)(g_h1 + (size_t)(n0 + 1) * HID + jn0) = a;
            *(float4*)(g_h1 + (size_t)(n0 + 1) * HID + jn0 + 4) = c;
        }
    }
}

// Layer 1: h2 = relu(mean1 @ Wn1 + h1 @ Ws1 + b1); out = h2 @ fc_w + fc_b. K = 128
__global__ __launch_bounds__(256, 1)
void layer1_kernel(const float* __restrict__ Wn,
                   const float* __restrict__ Ws,
                   const float* __restrict__ b,
                   const float* __restrict__ fcw,
                   const float* __restrict__ fcb,
                   float* __restrict__ out) {
    extern __shared__ float sh[];
    float* sWn = sh;                       // 128*128 = 16384
    float* sWs = sWn + HID * HID;          // 16384
    float* sM  = sWs + HID * HID;          // 4224
    float* sX  = sM + 32 * ROWP;           // 4224
    float* sFc = sX + 32 * ROWP;           // 258

    int t = threadIdx.x;
    for (int i = t; i < HID * HID; i += 256) { sWn[i] = Wn[i]; sWs[i] = Ws[i]; }
    if (t < 256) sFc[t] = fcw[t];
    if (t < 2) sFc[256 + t] = fcb[t];

    int nodeBase = blockIdx.x * 128;
    int jn0 = (t >> 4) * 8;
    int in0 = (t & 15) * 8;

    ull acc[4][8];
#pragma unroll
    for (int jj = 0; jj < 8; jj++) {
        ull bb = pack2(__ldg(&b[jn0 + jj]));
#pragma unroll
        for (int p = 0; p < 4; p++) acc[p][jj] = bb;
    }

    for (int s = 0; s < HID / 32; s++) {
        __syncthreads();
        for (int r = t; r < 128 * 8; r += 256) {
            int node = r >> 3;
            int kq = (r & 7) * 4;
            int gn = nodeBase + node;
            float4 vm = make_float4(0.f, 0.f, 0.f, 0.f), vx = vm;
            if (gn < N_NODES) {
                vm = *(const float4*)(g_mean1 + (size_t)gn * HID + s * 32 + kq);
                vx = *(const float4*)(g_h1    + (size_t)gn * HID + s * 32 + kq);
            }
            sM[(kq + 0) * ROWP + node] = vm.x; sM[(kq + 1) * ROWP + node] = vm.y;
            sM[(kq + 2) * ROWP + node] = vm.z; sM[(kq + 3) * ROWP + node] = vm.w;
            sX[(kq + 0) * ROWP + node] = vx.x; sX[(kq + 1) * ROWP + node] = vx.y;
            sX[(kq + 2) * ROWP + node] = vx.z; sX[(kq + 3) * ROWP + node] = vx.w;
        }
        __syncthreads();
#pragma unroll 2
        for (int k = 0; k < 32; k++) {
            const ull* rowM = (const ull*)(sM + k * ROWP) + (in0 >> 1);
            const ull* rowX = (const ull*)(sX + k * ROWP) + (in0 >> 1);
            ull m[4], xv[4];
#pragma unroll
            for (int p = 0; p < 4; p++) { m[p] = rowM[p]; xv[p] = rowX[p]; }
            const float* wnr = sWn + (s * 32 + k) * HID + jn0;
            const float* wsr = sWs + (s * 32 + k) * HID + jn0;
            float4 wna = *(const float4*)wnr, wnb = *(const float4*)(wnr + 4);
            float4 wsa = *(const float4*)wsr, wsb = *(const float4*)(wsr + 4);
            float wn[8] = {wna.x, wna.y, wna.z, wna.w, wnb.x, wnb.y, wnb.z, wnb.w};
            float ws[8] = {wsa.x, wsa.y, wsa.z, wsa.w, wsb.x, wsb.y, wsb.z, wsb.w};
#pragma unroll
            for (int jj = 0; jj < 8; jj++) {
                ull wn2 = pack2(wn[jj]);
#pragma unroll
                for (int p = 0; p < 4; p++) fma2(acc[p][jj], m[p], wn2);
                ull ws2 = pack2(ws[jj]);
#pragma unroll
                for (int p = 0; p < 4; p++) fma2(acc[p][jj], xv[p], ws2);
            }
        }
    }
    __syncthreads();   // weights dead; reuse as h2 staging [128][132]

    float* sH = sWn;
#pragma unroll
    for (int p = 0; p < 4; p++) {
#pragma unroll
        for (int jj = 0; jj < 8; jj++) {
            float2 v = unpack2(acc[p][jj]);
            sH[(in0 + 2 * p)     * ROWP + jn0 + jj] = fmaxf(v.x, 0.f);
            sH[(in0 + 2 * p + 1) * ROWP + jn0 + jj] = fmaxf(v.y, 0.f);
        }
    }
    __syncthreads();

    // fused FC: warp w handles 16 nodes; lane covers 4 channels
    int w = t >> 5, lane = t & 31;
    float fb0 = sFc[256], fb1 = sFc[257];
    float fw0[4], fw1[4];
#pragma unroll
    for (int q = 0; q < 4; q++) {
        fw0[q] = sFc[(lane * 4 + q) * 2 + 0];
        fw1[q] = sFc[(lane * 4 + q) * 2 + 1];
    }
    for (int ni = w * 16; ni < w * 16 + 16; ni++) {
        float4 h4 = *(const float4*)(sH + ni * ROWP + lane * 4);
        float p0 = h4.x * fw0[0] + h4.y * fw0[1] + h4.z * fw0[2] + h4.w * fw0[3];
        float p1 = h4.x * fw1[0] + h4.y * fw1[1] + h4.z * fw1[2] + h4.w * fw1[3];
#pragma unroll
        for (int off = 16; off > 0; off >>= 1) {
            p0 += __shfl_xor_sync(0xFFFFFFFF, p0, off);
            p1 += __shfl_xor_sync(0xFFFFFFFF, p1, off);
        }
        int node = nodeBase + ni;
        if (lane == 0 && node < N_NODES) {
            out[(size_t)node * 2 + 0] = p0 + fb0;
            out[(size_t)node * 2 + 1] = p1 + fb1;
        }
    }
}

// ---------------------------------------------------------------------------
extern "C" void kernel_launch(void* const* d_in, const int* in_sizes, int n_in,
                              void* d_out, int out_size) {
    const float* x    = (const float*)d_in[0];
    const int*   ei   = (const int*)d_in[1];     // int32 (JAX x64 disabled)
    const float* Wn0  = (const float*)d_in[2];
    const float* Ws0  = (const float*)d_in[3];
    const float* b0   = (const float*)d_in[4];
    const float* Wn1  = (const float*)d_in[5];
    const float* Ws1  = (const float*)d_in[6];
    const float* b1   = (const float*)d_in[7];
    const float* fcw  = (const float*)d_in[8];
    const float* fcb  = (const float*)d_in[9];
    float* out = (float*)d_out;

    // CSR build
    zero_deg_kernel<<<(N_NODES + 255) / 256, 256>>>();
    hist_kernel<<<(N_EDGES + 255) / 256, 256>>>(ei);
    scan_kernel<<<1, 1024>>>();
    fill_kernel<<<(N_EDGES + 255) / 256, 256>>>(ei);

    int gemmBlocks = (N_NODES + 127) / 128;

    // Layer 0
    gather0_kernel<<<(N_NODES + 7) / 8, 256>>>(x);
    {
        int smem0 = (2 * IN_CH * HID + 2 * 32 * ROWP) * (int)sizeof(float);  // ~97KB
        cudaFuncSetAttribute(layer0_kernel,
                             cudaFuncAttributeMaxDynamicSharedMemorySize, smem0);
        layer0_kernel<<<gemmBlocks, 256, smem0>>>(x, Wn0, Ws0, b0);
    }

    // Layer 1 + fused FC
    gather1_kernel<<<(N_NODES + 7) / 8, 256>>>();
    {
        int smem1 = (2 * HID * HID + 2 * 32 * ROWP + 258) * (int)sizeof(float); // ~162KB
        cudaFuncSetAttribute(layer1_kernel,
                             cudaFuncAttributeMaxDynamicSharedMemorySize, smem1);
        layer1_kernel<<<gemmBlocks, 256, smem1>>>(Wn1, Ws1, b1, fcw, fcb, out);
    }
}